// round 2
// baseline (speedup 1.0000x reference)
#include <cuda_runtime.h>
#include <math.h>

#define NN 50000
#define EE 800000

// ---------------- scratch (device globals; no allocation) ----------------
__device__ int   g_is64;
__device__ float g_deg[NN];
__device__ float g_norm[EE];
__device__ int   g_src[EE];
__device__ int   g_dst[EE];
__device__ float g_h0a[NN * 64];
__device__ float g_h0b[NN * 64];
__device__ float g_h1[NN * 64];
__device__ float g_h2[NN * 64];
__device__ float g_h3[NN * 64];

// ---------------- kernels ----------------

// Decide whether edge_index is int64 or int32. Indices are < 50000, so if the
// buffer is int64 every odd 32-bit word is 0. If int32, odd words are uniform
// random node ids (~never all zero across 512 samples). Deterministic.
__global__ void detect_kernel(const int* __restrict__ w) {
    int allzero = 1;
    for (int i = 1; i < 1024; i += 2)
        if (w[i] != 0) { allzero = 0; break; }
    g_is64 = allzero;
}

// Extract src/dst as int32 regardless of stored dtype. Layout (2, E):
// int64: src[e] = w[2e],      dst[e] = w[2*(E+e)]
// int32: src[e] = w[e],       dst[e] = w[E+e]
__global__ __launch_bounds__(256) void build_idx_kernel(const int* __restrict__ w) {
    int e = blockIdx.x * blockDim.x + threadIdx.x;
    if (e >= EE) return;
    int s, d;
    if (g_is64) {
        s = w[2 * e];
        d = w[2 * (EE + e)];
    } else {
        s = w[e];
        d = w[EE + e];
    }
    g_src[e] = s;
    g_dst[e] = d;
}

__global__ __launch_bounds__(256) void zero_kernel(float* p, int n) {
    int i = blockIdx.x * blockDim.x + threadIdx.x;
    if (i < n) p[i] = 0.0f;
}

__global__ __launch_bounds__(256) void deg_kernel(const float* __restrict__ ea) {
    int e = blockIdx.x * blockDim.x + threadIdx.x;
    if (e < EE) atomicAdd(&g_deg[g_dst[e]], ea[e]);
}

__global__ __launch_bounds__(256) void norm_kernel(const float* __restrict__ ea) {
    int e = blockIdx.x * blockDim.x + threadIdx.x;
    if (e < EE) {
        float ds = g_deg[g_src[e]];
        float dd = g_deg[g_dst[e]];
        float ns = ds > 0.0f ? rsqrtf(ds) : 0.0f;
        float nd = dd > 0.0f ? rsqrtf(dd) : 0.0f;
        g_norm[e] = ns * ea[e] * nd;
    }
}

__global__ __launch_bounds__(256) void concat_kernel(const float* __restrict__ x,
                                                     const float* __restrict__ pos) {
    int n = blockIdx.x * blockDim.x + threadIdx.x;
    if (n < NN) {
        float* o = &g_h0a[n * 8];
#pragma unroll
        for (int i = 0; i < 6; i++) o[i] = x[n * 6 + i];
        o[6] = pos[n * 2 + 0];
        o[7] = pos[n * 2 + 1];
    }
}

// scatter: h_out[dst] += norm * h_in[src], one thread per (edge, feature)
template <int F>
__global__ __launch_bounds__(256) void scatter_kernel(const float* __restrict__ hin,
                                                      float* __restrict__ hout) {
    int tid = blockIdx.x * blockDim.x + threadIdx.x;
    if (tid >= EE * F) return;
    int e = tid / F;
    int f = tid - e * F;
    float w = g_norm[e];
    int s = g_src[e];
    int d = g_dst[e];
    float v = w * hin[s * F + f];
    atomicAdd(&hout[d * F + f], v);
}

// out[n][j] = b[j] + sum_k sum_f h_k[n][f] * W[k][f][j]   (+ optional ReLU)
template <int FIN, int FOUT, bool RELU>
__global__ __launch_bounds__(256) void gemm4_kernel(const float* __restrict__ h0,
                                                    const float* __restrict__ h1,
                                                    const float* __restrict__ h2,
                                                    const float* __restrict__ h3,
                                                    const float* __restrict__ W,
                                                    const float* __restrict__ b,
                                                    float* __restrict__ out) {
    int tid = blockIdx.x * blockDim.x + threadIdx.x;
    if (tid >= NN * FOUT) return;
    int n = tid / FOUT;
    int j = tid - n * FOUT;
    const float* hs[4] = {h0 + n * FIN, h1 + n * FIN, h2 + n * FIN, h3 + n * FIN};
    float acc = b[j];
#pragma unroll
    for (int k = 0; k < 4; k++) {
        const float* w = W + k * FIN * FOUT + j;
        const float* h = hs[k];
#pragma unroll
        for (int f = 0; f < FIN; f++) acc = fmaf(h[f], w[f * FOUT], acc);
    }
    if (RELU) acc = fmaxf(acc, 0.0f);
    out[n * FOUT + j] = acc;
}

__global__ __launch_bounds__(256) void logsoftmax_kernel(float* __restrict__ out) {
    int n = blockIdx.x * blockDim.x + threadIdx.x;
    if (n >= NN) return;
    float v[10];
    float m = -1e30f;
#pragma unroll
    for (int i = 0; i < 10; i++) {
        v[i] = out[n * 10 + i];
        m = fmaxf(m, v[i]);
    }
    float s = 0.0f;
#pragma unroll
    for (int i = 0; i < 10; i++) s += expf(v[i] - m);
    float l = logf(s) + m;
#pragma unroll
    for (int i = 0; i < 10; i++) out[n * 10 + i] = v[i] - l;
}

// ---------------- host ----------------
static inline int cdiv(int a, int b) { return (a + b - 1) / b; }

extern "C" void kernel_launch(void* const* d_in, const int* in_sizes, int n_in,
                              void* d_out, int out_size) {
    const float* x   = (const float*)d_in[0];       // (N, 6)
    const float* pos = (const float*)d_in[1];       // (N, 2)
    const float* ea  = (const float*)d_in[2];       // (E,)
    const float* W1  = (const float*)d_in[3];       // (4, 8, 64)
    const float* b1  = (const float*)d_in[4];       // (64,)
    const float* W2  = (const float*)d_in[5];       // (4, 64, 64)
    const float* b2  = (const float*)d_in[6];       // (64,)
    const float* W3  = (const float*)d_in[7];       // (4, 64, 10)
    const float* b3  = (const float*)d_in[8];       // (10,)
    const int* ei    = (const int*)d_in[9];         // (2, E) int32 or int64 words
    float* out = (float*)d_out;                     // (N, 10)

    float *deg, *h0a, *h0b, *h1, *h2, *h3;
    cudaGetSymbolAddress((void**)&deg, g_deg);
    cudaGetSymbolAddress((void**)&h0a, g_h0a);
    cudaGetSymbolAddress((void**)&h0b, g_h0b);
    cudaGetSymbolAddress((void**)&h1, g_h1);
    cudaGetSymbolAddress((void**)&h2, g_h2);
    cudaGetSymbolAddress((void**)&h3, g_h3);

    const int B = 256;

    // index extraction + degree + normalization coefficients
    detect_kernel<<<1, 1>>>(ei);
    build_idx_kernel<<<cdiv(EE, B), B>>>(ei);
    zero_kernel<<<cdiv(NN, B), B>>>(deg, NN);
    deg_kernel<<<cdiv(EE, B), B>>>(ea);
    norm_kernel<<<cdiv(EE, B), B>>>(ea);

    // h0 = concat(x, pos) -> (N, 8), compact
    concat_kernel<<<cdiv(NN, B), B>>>(x, pos);

    // ---------------- layer 1: FIN=8 -> 64, ReLU ----------------
    zero_kernel<<<cdiv(NN * 8, B), B>>>(h1, NN * 8);
    scatter_kernel<8><<<cdiv(EE * 8, B), B>>>(h0a, h1);
    zero_kernel<<<cdiv(NN * 8, B), B>>>(h2, NN * 8);
    scatter_kernel<8><<<cdiv(EE * 8, B), B>>>(h1, h2);
    zero_kernel<<<cdiv(NN * 8, B), B>>>(h3, NN * 8);
    scatter_kernel<8><<<cdiv(EE * 8, B), B>>>(h2, h3);
    gemm4_kernel<8, 64, true><<<cdiv(NN * 64, B), B>>>(h0a, h1, h2, h3, W1, b1, h0b);

    // ---------------- layer 2: 64 -> 64, ReLU ----------------
    zero_kernel<<<cdiv(NN * 64, B), B>>>(h1, NN * 64);
    scatter_kernel<64><<<cdiv(EE * 64, B), B>>>(h0b, h1);
    zero_kernel<<<cdiv(NN * 64, B), B>>>(h2, NN * 64);
    scatter_kernel<64><<<cdiv(EE * 64, B), B>>>(h1, h2);
    zero_kernel<<<cdiv(NN * 64, B), B>>>(h3, NN * 64);
    scatter_kernel<64><<<cdiv(EE * 64, B), B>>>(h2, h3);
    gemm4_kernel<64, 64, true><<<cdiv(NN * 64, B), B>>>(h0b, h1, h2, h3, W2, b2, h0a);

    // ---------------- layer 3: 64 -> 10, then log_softmax ----------------
    zero_kernel<<<cdiv(NN * 64, B), B>>>(h1, NN * 64);
    scatter_kernel<64><<<cdiv(EE * 64, B), B>>>(h0a, h1);
    zero_kernel<<<cdiv(NN * 64, B), B>>>(h2, NN * 64);
    scatter_kernel<64><<<cdiv(EE * 64, B), B>>>(h1, h2);
    zero_kernel<<<cdiv(NN * 64, B), B>>>(h3, NN * 64);
    scatter_kernel<64><<<cdiv(EE * 64, B), B>>>(h2, h3);
    gemm4_kernel<64, 10, false><<<cdiv(NN * 10, B), B>>>(h0a, h1, h2, h3, W3, b3, out);

    logsoftmax_kernel<<<cdiv(NN, B), B>>>(out);
}

// round 3
// speedup vs baseline: 2.1620x; 2.1620x over previous
#include <cuda_runtime.h>
#include <math.h>

#define NN 50000
#define EE 800000

// ---------------- scratch (device globals; no allocation) ----------------
__device__ int   g_is64;
__device__ float g_deg[NN];
__device__ float g_norm[EE];
__device__ int   g_src[EE];
__device__ int   g_dst[EE];
__device__ int   g_cnt[NN];
__device__ int   g_rowptr[NN + 1];
__device__ int   g_woff[NN];
__device__ int   g_cs_src[EE];
__device__ float g_cs_val[EE];
__device__ float g_h0a[NN * 64];
__device__ float g_h0b[NN * 64];
__device__ float g_h1[NN * 64];
__device__ float g_h2[NN * 64];
__device__ float g_h3[NN * 64];

// ---------------- index extraction ----------------
__global__ void detect_kernel(const int* __restrict__ w) {
    int allzero = 1;
    for (int i = 1; i < 1024; i += 2)
        if (w[i] != 0) { allzero = 0; break; }
    g_is64 = allzero;
}

__global__ __launch_bounds__(256) void build_idx_kernel(const int* __restrict__ w) {
    int e = blockIdx.x * blockDim.x + threadIdx.x;
    if (e >= EE) return;
    int s, d;
    if (g_is64) { s = w[2 * e]; d = w[2 * (EE + e)]; }
    else        { s = w[e];     d = w[EE + e]; }
    g_src[e] = s;
    g_dst[e] = d;
}

// ---------------- deg / norm ----------------
__global__ __launch_bounds__(256) void zero_f_kernel(float* p, int n) {
    int i = blockIdx.x * blockDim.x + threadIdx.x;
    if (i < n) p[i] = 0.0f;
}
__global__ __launch_bounds__(256) void zero_i_kernel(int* p, int n) {
    int i = blockIdx.x * blockDim.x + threadIdx.x;
    if (i < n) p[i] = 0;
}

__global__ __launch_bounds__(256) void deg_kernel(const float* __restrict__ ea) {
    int e = blockIdx.x * blockDim.x + threadIdx.x;
    if (e < EE) atomicAdd(&g_deg[g_dst[e]], ea[e]);
}

__global__ __launch_bounds__(256) void norm_kernel(const float* __restrict__ ea) {
    int e = blockIdx.x * blockDim.x + threadIdx.x;
    if (e < EE) {
        float ds = g_deg[g_src[e]];
        float dd = g_deg[g_dst[e]];
        float ns = ds > 0.0f ? rsqrtf(ds) : 0.0f;
        float nd = dd > 0.0f ? rsqrtf(dd) : 0.0f;
        g_norm[e] = ns * ea[e] * nd;
    }
}

// ---------------- CSR build ----------------
__global__ __launch_bounds__(256) void count_kernel() {
    int e = blockIdx.x * blockDim.x + threadIdx.x;
    if (e < EE) atomicAdd(&g_cnt[g_dst[e]], 1);
}

// single-block inclusive scan over g_cnt -> g_rowptr (exclusive form)
__global__ __launch_bounds__(1024) void scan_kernel() {
    __shared__ int sdata[1024];
    __shared__ int carry;
    if (threadIdx.x == 0) carry = 0;
    __syncthreads();
    for (int base = 0; base < NN; base += 1024) {
        int i = base + threadIdx.x;
        int v = (i < NN) ? g_cnt[i] : 0;
        sdata[threadIdx.x] = v;
        __syncthreads();
        for (int off = 1; off < 1024; off <<= 1) {
            int t = (threadIdx.x >= off) ? sdata[threadIdx.x - off] : 0;
            __syncthreads();
            sdata[threadIdx.x] += t;
            __syncthreads();
        }
        if (i < NN) g_rowptr[i + 1] = carry + sdata[threadIdx.x];
        __syncthreads();
        if (threadIdx.x == 0) carry += sdata[1023];
        __syncthreads();
    }
    if (threadIdx.x == 0) g_rowptr[0] = 0;
}

__global__ __launch_bounds__(256) void copy_off_kernel() {
    int i = blockIdx.x * blockDim.x + threadIdx.x;
    if (i < NN) g_woff[i] = g_rowptr[i];
}

__global__ __launch_bounds__(256) void place_kernel() {
    int e = blockIdx.x * blockDim.x + threadIdx.x;
    if (e >= EE) return;
    int d = g_dst[e];
    int pos = atomicAdd(&g_woff[d], 1);
    g_cs_src[pos] = g_src[e];
    g_cs_val[pos] = g_norm[e];
}

// ---------------- features ----------------
__global__ __launch_bounds__(256) void concat_kernel(const float* __restrict__ x,
                                                     const float* __restrict__ pos) {
    int n = blockIdx.x * blockDim.x + threadIdx.x;
    if (n < NN) {
        float* o = &g_h0a[n * 8];
#pragma unroll
        for (int i = 0; i < 6; i++) o[i] = x[n * 6 + i];
        o[6] = pos[n * 2 + 0];
        o[7] = pos[n * 2 + 1];
    }
}

// ---------------- CSR gather hops (no atomics, no pre-zero) ----------------
// F=64: one warp per dst node; lane owns features lane and lane+32.
__global__ __launch_bounds__(256) void gather64_kernel(const float* __restrict__ hin,
                                                       float* __restrict__ hout) {
    int warp = (blockIdx.x * blockDim.x + threadIdx.x) >> 5;
    int lane = threadIdx.x & 31;
    if (warp >= NN) return;
    int beg = g_rowptr[warp];
    int end = g_rowptr[warp + 1];
    float a0 = 0.0f, a1 = 0.0f;
    for (int b = beg; b < end; b += 32) {
        int idx = b + lane;
        int s = (idx < end) ? g_cs_src[idx] : 0;
        float w = (idx < end) ? g_cs_val[idx] : 0.0f;
        int m = min(32, end - b);
        for (int j = 0; j < m; j++) {
            int sj = __shfl_sync(0xffffffffu, s, j);
            float wj = __shfl_sync(0xffffffffu, w, j);
            const float* row = hin + sj * 64;
            a0 = fmaf(wj, row[lane], a0);
            a1 = fmaf(wj, row[lane + 32], a1);
        }
    }
    hout[warp * 64 + lane] = a0;
    hout[warp * 64 + lane + 32] = a1;
}

// F=8: one thread per (node, feature)
__global__ __launch_bounds__(256) void gather8_kernel(const float* __restrict__ hin,
                                                      float* __restrict__ hout) {
    int tid = blockIdx.x * blockDim.x + threadIdx.x;
    if (tid >= NN * 8) return;
    int n = tid >> 3;
    int f = tid & 7;
    int beg = g_rowptr[n];
    int end = g_rowptr[n + 1];
    float acc = 0.0f;
    for (int e = beg; e < end; e++) {
        acc = fmaf(g_cs_val[e], hin[g_cs_src[e] * 8 + f], acc);
    }
    hout[n * 8 + f] = acc;
}

// ---------------- dense: out[n][j] = b[j] + sum_k h_k[n] @ W[k] ----------------
// 4 outputs per thread, float4 W loads (FOUT % 4 == 0)
template <int FIN, int FOUT, bool RELU>
__global__ __launch_bounds__(256) void gemm4v_kernel(const float* __restrict__ h0,
                                                     const float* __restrict__ h1,
                                                     const float* __restrict__ h2,
                                                     const float* __restrict__ h3,
                                                     const float* __restrict__ W,
                                                     const float* __restrict__ b,
                                                     float* __restrict__ out) {
    constexpr int J4 = FOUT / 4;
    int tid = blockIdx.x * blockDim.x + threadIdx.x;
    if (tid >= NN * J4) return;
    int n = tid / J4;
    int j = (tid - n * J4) * 4;
    float4 acc = *(const float4*)&b[j];
    const float* hs[4] = {h0 + n * FIN, h1 + n * FIN, h2 + n * FIN, h3 + n * FIN};
#pragma unroll
    for (int k = 0; k < 4; k++) {
        const float* h = hs[k];
        const float* w = W + k * FIN * FOUT + j;
#pragma unroll
        for (int f = 0; f < FIN; f++) {
            float hf = h[f];
            float4 wv = *(const float4*)&w[f * FOUT];
            acc.x = fmaf(hf, wv.x, acc.x);
            acc.y = fmaf(hf, wv.y, acc.y);
            acc.z = fmaf(hf, wv.z, acc.z);
            acc.w = fmaf(hf, wv.w, acc.w);
        }
    }
    if (RELU) {
        acc.x = fmaxf(acc.x, 0.0f); acc.y = fmaxf(acc.y, 0.0f);
        acc.z = fmaxf(acc.z, 0.0f); acc.w = fmaxf(acc.w, 0.0f);
    }
    *(float4*)&out[n * FOUT + j] = acc;
}

// scalar version for FOUT=10 (layer 3)
template <int FIN, int FOUT, bool RELU>
__global__ __launch_bounds__(256) void gemm4s_kernel(const float* __restrict__ h0,
                                                     const float* __restrict__ h1,
                                                     const float* __restrict__ h2,
                                                     const float* __restrict__ h3,
                                                     const float* __restrict__ W,
                                                     const float* __restrict__ b,
                                                     float* __restrict__ out) {
    int tid = blockIdx.x * blockDim.x + threadIdx.x;
    if (tid >= NN * FOUT) return;
    int n = tid / FOUT;
    int j = tid - n * FOUT;
    const float* hs[4] = {h0 + n * FIN, h1 + n * FIN, h2 + n * FIN, h3 + n * FIN};
    float acc = b[j];
#pragma unroll
    for (int k = 0; k < 4; k++) {
        const float* w = W + k * FIN * FOUT + j;
        const float* h = hs[k];
#pragma unroll
        for (int f = 0; f < FIN; f++) acc = fmaf(h[f], w[f * FOUT], acc);
    }
    if (RELU) acc = fmaxf(acc, 0.0f);
    out[n * FOUT + j] = acc;
}

__global__ __launch_bounds__(256) void logsoftmax_kernel(float* __restrict__ out) {
    int n = blockIdx.x * blockDim.x + threadIdx.x;
    if (n >= NN) return;
    float v[10];
    float m = -1e30f;
#pragma unroll
    for (int i = 0; i < 10; i++) {
        v[i] = out[n * 10 + i];
        m = fmaxf(m, v[i]);
    }
    float s = 0.0f;
#pragma unroll
    for (int i = 0; i < 10; i++) s += expf(v[i] - m);
    float l = logf(s) + m;
#pragma unroll
    for (int i = 0; i < 10; i++) out[n * 10 + i] = v[i] - l;
}

// ---------------- host ----------------
static inline int cdiv(int a, int b) { return (a + b - 1) / b; }

extern "C" void kernel_launch(void* const* d_in, const int* in_sizes, int n_in,
                              void* d_out, int out_size) {
    const float* x   = (const float*)d_in[0];
    const float* pos = (const float*)d_in[1];
    const float* ea  = (const float*)d_in[2];
    const float* W1  = (const float*)d_in[3];
    const float* b1  = (const float*)d_in[4];
    const float* W2  = (const float*)d_in[5];
    const float* b2  = (const float*)d_in[6];
    const float* W3  = (const float*)d_in[7];
    const float* b3  = (const float*)d_in[8];
    const int* ei    = (const int*)d_in[9];
    float* out = (float*)d_out;

    float *deg, *h0a, *h0b, *h1, *h2, *h3;
    int *cnt;
    cudaGetSymbolAddress((void**)&deg, g_deg);
    cudaGetSymbolAddress((void**)&cnt, g_cnt);
    cudaGetSymbolAddress((void**)&h0a, g_h0a);
    cudaGetSymbolAddress((void**)&h0b, g_h0b);
    cudaGetSymbolAddress((void**)&h1, g_h1);
    cudaGetSymbolAddress((void**)&h2, g_h2);
    cudaGetSymbolAddress((void**)&h3, g_h3);

    const int B = 256;

    // indices, degrees, norms
    detect_kernel<<<1, 1>>>(ei);
    build_idx_kernel<<<cdiv(EE, B), B>>>(ei);
    zero_f_kernel<<<cdiv(NN, B), B>>>(deg, NN);
    deg_kernel<<<cdiv(EE, B), B>>>(ea);
    norm_kernel<<<cdiv(EE, B), B>>>(ea);

    // CSR by dst
    zero_i_kernel<<<cdiv(NN, B), B>>>(cnt, NN);
    count_kernel<<<cdiv(EE, B), B>>>();
    scan_kernel<<<1, 1024>>>();
    copy_off_kernel<<<cdiv(NN, B), B>>>();
    place_kernel<<<cdiv(EE, B), B>>>();

    // h0 = concat(x, pos)
    concat_kernel<<<cdiv(NN, B), B>>>(x, pos);

    // ---------------- layer 1: 8 -> 64, ReLU ----------------
    gather8_kernel<<<cdiv(NN * 8, B), B>>>(h0a, h1);
    gather8_kernel<<<cdiv(NN * 8, B), B>>>(h1, h2);
    gather8_kernel<<<cdiv(NN * 8, B), B>>>(h2, h3);
    gemm4v_kernel<8, 64, true><<<cdiv(NN * 16, B), B>>>(h0a, h1, h2, h3, W1, b1, h0b);

    // ---------------- layer 2: 64 -> 64, ReLU ----------------
    gather64_kernel<<<cdiv(NN * 32, B), B>>>(h0b, h1);
    gather64_kernel<<<cdiv(NN * 32, B), B>>>(h1, h2);
    gather64_kernel<<<cdiv(NN * 32, B), B>>>(h2, h3);
    gemm4v_kernel<64, 64, true><<<cdiv(NN * 16, B), B>>>(h0b, h1, h2, h3, W2, b2, h0a);

    // ---------------- layer 3: 64 -> 10 + log_softmax ----------------
    gather64_kernel<<<cdiv(NN * 32, B), B>>>(h0a, h1);
    gather64_kernel<<<cdiv(NN * 32, B), B>>>(h1, h2);
    gather64_kernel<<<cdiv(NN * 32, B), B>>>(h2, h3);
    gemm4s_kernel<64, 10, false><<<cdiv(NN * 10, B), B>>>(h0a, h1, h2, h3, W3, b3, out);

    logsoftmax_kernel<<<cdiv(NN, B), B>>>(out);
}

// round 4
// speedup vs baseline: 2.2748x; 1.0522x over previous
#include <cuda_runtime.h>
#include <math.h>

#define NN 50000
#define EE 800000

// ---------------- scratch (device globals; no allocation) ----------------
__device__ int   g_is64;
__device__ float g_deg[NN];
__device__ int   g_src[EE];
__device__ int   g_dst[EE];
__device__ int   g_cnt[NN];
__device__ int   g_rowptr[NN + 1];
__device__ int   g_woff[NN];
__device__ int   g_cs_src[EE];
__device__ float g_cs_val[EE];
__device__ float g_h0a[NN * 64];
__device__ float g_h0b[NN * 64];
__device__ float g_h1[NN * 64];
__device__ float g_h2[NN * 64];
__device__ float g_h3[NN * 64];

// ---------------- preprocessing ----------------
__global__ void detect_kernel(const int* __restrict__ w) {
    int allzero = 1;
    for (int i = 1; i < 1024; i += 2)
        if (w[i] != 0) { allzero = 0; break; }
    g_is64 = allzero;
}

// build src/dst (int32 regardless of stored dtype) + zero deg/cnt
__global__ __launch_bounds__(256) void build_zero_kernel(const int* __restrict__ w) {
    int e = blockIdx.x * blockDim.x + threadIdx.x;
    if (e < EE) {
        int s, d;
        if (g_is64) { s = w[2 * e]; d = w[2 * (EE + e)]; }
        else        { s = w[e];     d = w[EE + e]; }
        g_src[e] = s;
        g_dst[e] = d;
    }
    if (e < NN) { g_deg[e] = 0.0f; g_cnt[e] = 0; }
}

__global__ __launch_bounds__(256) void degcnt_kernel(const float* __restrict__ ea) {
    int e = blockIdx.x * blockDim.x + threadIdx.x;
    if (e < EE) {
        int d = g_dst[e];
        atomicAdd(&g_deg[d], ea[e]);
        atomicAdd(&g_cnt[d], 1);
    }
}

// single-block scan: rowptr (exclusive starts) + woff, shfl-based, 2-pass
__global__ __launch_bounds__(1024) void scan_kernel() {
    const int CH = (NN + 1023) / 1024;  // 49
    int t = threadIdx.x;
    int base = t * CH;
    int sum = 0;
    for (int i = 0; i < CH; i++) {
        int idx = base + i;
        if (idx < NN) sum += g_cnt[idx];
    }
    int lane = t & 31, wid = t >> 5;
    int inc = sum;
#pragma unroll
    for (int off = 1; off < 32; off <<= 1) {
        int v = __shfl_up_sync(0xffffffffu, inc, off);
        if (lane >= off) inc += v;
    }
    __shared__ int ws[32];
    if (lane == 31) ws[wid] = inc;
    __syncthreads();
    if (wid == 0) {
        int v2 = ws[lane];
#pragma unroll
        for (int off = 1; off < 32; off <<= 1) {
            int u = __shfl_up_sync(0xffffffffu, v2, off);
            if (lane >= off) v2 += u;
        }
        ws[lane] = v2;
    }
    __syncthreads();
    int run = (wid > 0 ? ws[wid - 1] : 0) + inc - sum;  // exclusive offset
    for (int i = 0; i < CH; i++) {
        int idx = base + i;
        if (idx < NN) {
            g_rowptr[idx] = run;
            g_woff[idx] = run;
            run += g_cnt[idx];
        }
    }
    if (t == 1023) g_rowptr[NN] = run;
}

// compute norm + place into CSR buckets
__global__ __launch_bounds__(256) void place_kernel(const float* __restrict__ ea) {
    int e = blockIdx.x * blockDim.x + threadIdx.x;
    if (e >= EE) return;
    int s = g_src[e];
    int d = g_dst[e];
    float ds = g_deg[s];
    float dd = g_deg[d];
    float ns = ds > 0.0f ? rsqrtf(ds) : 0.0f;
    float nd = dd > 0.0f ? rsqrtf(dd) : 0.0f;
    int pos = atomicAdd(&g_woff[d], 1);
    g_cs_src[pos] = s;
    g_cs_val[pos] = ns * ea[e] * nd;
}

__global__ __launch_bounds__(256) void concat_kernel(const float* __restrict__ x,
                                                     const float* __restrict__ pos) {
    int n = blockIdx.x * blockDim.x + threadIdx.x;
    if (n < NN) {
        float* o = &g_h0a[n * 8];
#pragma unroll
        for (int i = 0; i < 6; i++) o[i] = x[n * 6 + i];
        o[6] = pos[n * 2 + 0];
        o[7] = pos[n * 2 + 1];
    }
}

// ---------------- CSR gather hops ----------------
// F=64: warp per node, lane owns features {lane, lane+32}; 4-edge unroll for MLP
__global__ __launch_bounds__(256) void gather64_kernel(const float* __restrict__ hin,
                                                       float* __restrict__ hout) {
    int warp = (blockIdx.x * blockDim.x + threadIdx.x) >> 5;
    int lane = threadIdx.x & 31;
    if (warp >= NN) return;
    int beg = g_rowptr[warp];
    int end = g_rowptr[warp + 1];
    float a00 = 0.0f, a01 = 0.0f, a10 = 0.0f, a11 = 0.0f;
    float a20 = 0.0f, a21 = 0.0f, a30 = 0.0f, a31 = 0.0f;
    for (int b = beg; b < end; b += 32) {
        int idx = b + lane;
        int s = (idx < end) ? g_cs_src[idx] : 0;
        float w = (idx < end) ? g_cs_val[idx] : 0.0f;
        int m = min(32, end - b);
        int j = 0;
        for (; j + 4 <= m; j += 4) {
            int s0 = __shfl_sync(0xffffffffu, s, j + 0);
            int s1 = __shfl_sync(0xffffffffu, s, j + 1);
            int s2 = __shfl_sync(0xffffffffu, s, j + 2);
            int s3 = __shfl_sync(0xffffffffu, s, j + 3);
            float w0 = __shfl_sync(0xffffffffu, w, j + 0);
            float w1 = __shfl_sync(0xffffffffu, w, j + 1);
            float w2 = __shfl_sync(0xffffffffu, w, j + 2);
            float w3 = __shfl_sync(0xffffffffu, w, j + 3);
            const float* r0 = hin + s0 * 64;
            const float* r1 = hin + s1 * 64;
            const float* r2 = hin + s2 * 64;
            const float* r3 = hin + s3 * 64;
            float v00 = r0[lane], v01 = r0[lane + 32];
            float v10 = r1[lane], v11 = r1[lane + 32];
            float v20 = r2[lane], v21 = r2[lane + 32];
            float v30 = r3[lane], v31 = r3[lane + 32];
            a00 = fmaf(w0, v00, a00); a01 = fmaf(w0, v01, a01);
            a10 = fmaf(w1, v10, a10); a11 = fmaf(w1, v11, a11);
            a20 = fmaf(w2, v20, a20); a21 = fmaf(w2, v21, a21);
            a30 = fmaf(w3, v30, a30); a31 = fmaf(w3, v31, a31);
        }
        for (; j < m; j++) {
            int sj = __shfl_sync(0xffffffffu, s, j);
            float wj = __shfl_sync(0xffffffffu, w, j);
            const float* row = hin + sj * 64;
            a00 = fmaf(wj, row[lane], a00);
            a01 = fmaf(wj, row[lane + 32], a01);
        }
    }
    float f0 = (a00 + a10) + (a20 + a30);
    float f1 = (a01 + a11) + (a21 + a31);
    hout[warp * 64 + lane] = f0;
    hout[warp * 64 + lane + 32] = f1;
}

// small-F gathers: thread per (node, feature)
template <int F>
__global__ __launch_bounds__(256) void gatherF_kernel(const float* __restrict__ hin,
                                                      float* __restrict__ hout) {
    int tid = blockIdx.x * blockDim.x + threadIdx.x;
    if (tid >= NN * F) return;
    int n = tid / F;
    int f = tid - n * F;
    int beg = g_rowptr[n];
    int end = g_rowptr[n + 1];
    float a0 = 0.0f, a1 = 0.0f;
    int e = beg;
    for (; e + 2 <= end; e += 2) {
        a0 = fmaf(g_cs_val[e], hin[g_cs_src[e] * F + f], a0);
        a1 = fmaf(g_cs_val[e + 1], hin[g_cs_src[e + 1] * F + f], a1);
    }
    if (e < end) a0 = fmaf(g_cs_val[e], hin[g_cs_src[e] * F + f], a0);
    hout[tid] = a0 + a1;
}

// ---------------- dense GEMMs ----------------
// out[n][j] = b[j] + sum_k h_k[n] @ W[k], 4 outputs/thread, float4 W loads
template <int FIN, int FOUT, bool RELU>
__global__ __launch_bounds__(256) void gemm4v_kernel(const float* __restrict__ h0,
                                                     const float* __restrict__ h1,
                                                     const float* __restrict__ h2,
                                                     const float* __restrict__ h3,
                                                     const float* __restrict__ W,
                                                     const float* __restrict__ b,
                                                     float* __restrict__ out) {
    constexpr int J4 = FOUT / 4;
    int tid = blockIdx.x * blockDim.x + threadIdx.x;
    if (tid >= NN * J4) return;
    int n = tid / J4;
    int j = (tid - n * J4) * 4;
    float4 acc = *(const float4*)&b[j];
    const float* hs[4] = {h0 + n * FIN, h1 + n * FIN, h2 + n * FIN, h3 + n * FIN};
#pragma unroll
    for (int k = 0; k < 4; k++) {
        const float* h = hs[k];
        const float* w = W + k * FIN * FOUT + j;
#pragma unroll
        for (int f = 0; f < FIN; f++) {
            float hf = h[f];
            float4 wv = *(const float4*)&w[f * FOUT];
            acc.x = fmaf(hf, wv.x, acc.x);
            acc.y = fmaf(hf, wv.y, acc.y);
            acc.z = fmaf(hf, wv.z, acc.z);
            acc.w = fmaf(hf, wv.w, acc.w);
        }
    }
    if (RELU) {
        acc.x = fmaxf(acc.x, 0.0f); acc.y = fmaxf(acc.y, 0.0f);
        acc.z = fmaxf(acc.z, 0.0f); acc.w = fmaxf(acc.w, 0.0f);
    }
    *(float4*)&out[n * FOUT + j] = acc;
}

// single-slice gemm for Horner (layer 3): out = [add +] [bias +] h @ W
template <int FIN, int FOUT, bool BIAS, bool ADD>
__global__ __launch_bounds__(256) void gemm1_kernel(const float* __restrict__ h,
                                                    const float* __restrict__ W,
                                                    const float* __restrict__ b,
                                                    const float* __restrict__ add,
                                                    float* __restrict__ out) {
    int tid = blockIdx.x * blockDim.x + threadIdx.x;
    if (tid >= NN * FOUT) return;
    int n = tid / FOUT;
    int j = tid - n * FOUT;
    float acc = BIAS ? b[j] : 0.0f;
    if (ADD) acc += add[tid];
    const float* hr = h + n * FIN;
#pragma unroll
    for (int f = 0; f < FIN; f++) acc = fmaf(hr[f], W[f * FOUT + j], acc);
    out[tid] = acc;
}

__global__ __launch_bounds__(256) void logsoftmax_kernel(float* __restrict__ out) {
    int n = blockIdx.x * blockDim.x + threadIdx.x;
    if (n >= NN) return;
    float v[10];
    float m = -1e30f;
#pragma unroll
    for (int i = 0; i < 10; i++) {
        v[i] = out[n * 10 + i];
        m = fmaxf(m, v[i]);
    }
    float s = 0.0f;
#pragma unroll
    for (int i = 0; i < 10; i++) s += expf(v[i] - m);
    float l = logf(s) + m;
#pragma unroll
    for (int i = 0; i < 10; i++) out[n * 10 + i] = v[i] - l;
}

// ---------------- host ----------------
static inline int cdiv(int a, int b) { return (a + b - 1) / b; }

extern "C" void kernel_launch(void* const* d_in, const int* in_sizes, int n_in,
                              void* d_out, int out_size) {
    const float* x   = (const float*)d_in[0];
    const float* pos = (const float*)d_in[1];
    const float* ea  = (const float*)d_in[2];
    const float* W1  = (const float*)d_in[3];
    const float* b1  = (const float*)d_in[4];
    const float* W2  = (const float*)d_in[5];
    const float* b2  = (const float*)d_in[6];
    const float* W3  = (const float*)d_in[7];
    const float* b3  = (const float*)d_in[8];
    const int* ei    = (const int*)d_in[9];
    float* out = (float*)d_out;

    float *h0a, *h0b, *h1, *h2, *h3;
    cudaGetSymbolAddress((void**)&h0a, g_h0a);
    cudaGetSymbolAddress((void**)&h0b, g_h0b);
    cudaGetSymbolAddress((void**)&h1, g_h1);
    cudaGetSymbolAddress((void**)&h2, g_h2);
    cudaGetSymbolAddress((void**)&h3, g_h3);

    const int B = 256;

    // preprocessing: indices -> deg/cnt -> scan -> CSR place
    detect_kernel<<<1, 1>>>(ei);
    build_zero_kernel<<<cdiv(EE, B), B>>>(ei);
    degcnt_kernel<<<cdiv(EE, B), B>>>(ea);
    scan_kernel<<<1, 1024>>>();
    place_kernel<<<cdiv(EE, B), B>>>(ea);
    concat_kernel<<<cdiv(NN, B), B>>>(x, pos);

    // ---------------- layer 1: 8 -> 64, ReLU (hops at F=8) ----------------
    gatherF_kernel<8><<<cdiv(NN * 8, B), B>>>(h0a, h1);
    gatherF_kernel<8><<<cdiv(NN * 8, B), B>>>(h1, h2);
    gatherF_kernel<8><<<cdiv(NN * 8, B), B>>>(h2, h3);
    gemm4v_kernel<8, 64, true><<<cdiv(NN * 16, B), B>>>(h0a, h1, h2, h3, W1, b1, h0b);

    // ---------------- layer 2: 64 -> 64, ReLU (hops at F=64) ----------------
    gather64_kernel<<<cdiv(NN * 32, B), B>>>(h0b, h1);
    gather64_kernel<<<cdiv(NN * 32, B), B>>>(h1, h2);
    gather64_kernel<<<cdiv(NN * 32, B), B>>>(h2, h3);
    gemm4v_kernel<64, 64, true><<<cdiv(NN * 16, B), B>>>(h0b, h1, h2, h3, W2, b2, h0a);

    // ---------------- layer 3 (Horner): hops at F=10 ----------------
    // out = hW0 + b3 + A(hW1 + A(hW2 + A(hW3)))
    float* p = h1;
    float* q = h2;
    gemm1_kernel<64, 10, false, false><<<cdiv(NN * 10, B), B>>>(h0a, W3 + 3 * 640, nullptr, nullptr, p);
    gatherF_kernel<10><<<cdiv(NN * 10, B), B>>>(p, q);
    gemm1_kernel<64, 10, false, true><<<cdiv(NN * 10, B), B>>>(h0a, W3 + 2 * 640, nullptr, q, p);
    gatherF_kernel<10><<<cdiv(NN * 10, B), B>>>(p, q);
    gemm1_kernel<64, 10, false, true><<<cdiv(NN * 10, B), B>>>(h0a, W3 + 1 * 640, nullptr, q, p);
    gatherF_kernel<10><<<cdiv(NN * 10, B), B>>>(p, q);
    gemm1_kernel<64, 10, true, true><<<cdiv(NN * 10, B), B>>>(h0a, W3, b3, q, out);

    logsoftmax_kernel<<<cdiv(NN, B), B>>>(out);
}

// round 6
// speedup vs baseline: 2.7333x; 1.2016x over previous
#include <cuda_runtime.h>
#include <math.h>

#define NN 50000
#define EE 800000
#define SCAN_B 49  // ceil(NN/1024)

// ---------------- scratch (device globals; no allocation) ----------------
__device__ int   g_is64;
__device__ float g_deg[NN];
__device__ int   g_src[EE];
__device__ int   g_dst[EE];
__device__ int   g_cnt[NN];
__device__ int   g_bsum[SCAN_B];
__device__ int   g_boff[SCAN_B];
__device__ int   g_rowptr[NN + 1];
__device__ int   g_woff[NN];
__device__ int   g_cs_src[EE];
__device__ float g_cs_val[EE];
__device__ float g_h0a[NN * 64];
__device__ float g_h0b[NN * 64];
__device__ float g_h1[NN * 64];
__device__ float g_h2[NN * 64];
__device__ float g_h3[NN * 64];

// ---------------- preprocessing ----------------
__global__ void detect_kernel(const int* __restrict__ w) {
    int allzero = 1;
    for (int i = 1; i < 1024; i += 2)
        if (w[i] != 0) { allzero = 0; break; }
    g_is64 = allzero;
}

// build src/dst (int32 regardless of stored dtype) + zero deg/cnt
__global__ __launch_bounds__(256) void build_zero_kernel(const int* __restrict__ w) {
    int e = blockIdx.x * blockDim.x + threadIdx.x;
    if (e < EE) {
        int s, d;
        if (g_is64) { s = w[2 * e]; d = w[2 * (EE + e)]; }
        else        { s = w[e];     d = w[EE + e]; }
        g_src[e] = s;
        g_dst[e] = d;
    }
    if (e < NN) { g_deg[e] = 0.0f; g_cnt[e] = 0; }
}

__global__ __launch_bounds__(256) void degcnt_kernel(const float* __restrict__ ea) {
    int e = blockIdx.x * blockDim.x + threadIdx.x;
    if (e < EE) {
        int d = g_dst[e];
        atomicAdd(&g_deg[d], ea[e]);
        atomicAdd(&g_cnt[d], 1);
    }
}

// ---------------- decoupled scan (all accesses coalesced) ----------------
// phase 1: per-block reduce of 1024 cnt values
__global__ __launch_bounds__(1024) void scan_reduce_kernel() {
    int i = blockIdx.x * 1024 + threadIdx.x;
    int v = (i < NN) ? g_cnt[i] : 0;
    int lane = threadIdx.x & 31, wid = threadIdx.x >> 5;
#pragma unroll
    for (int off = 16; off > 0; off >>= 1) v += __shfl_down_sync(0xffffffffu, v, off);
    __shared__ int ws[32];
    if (lane == 0) ws[wid] = v;
    __syncthreads();
    if (wid == 0) {
        int u = ws[lane];
#pragma unroll
        for (int off = 16; off > 0; off >>= 1) u += __shfl_down_sync(0xffffffffu, u, off);
        if (lane == 0) g_bsum[blockIdx.x] = u;
    }
}

// phase 2: exclusive scan of SCAN_B partials (one block, 64 threads)
__global__ __launch_bounds__(64) void scan_spine_kernel() {
    int t = threadIdx.x;
    int v = (t < SCAN_B) ? g_bsum[t] : 0;
    int lane = t & 31, wid = t >> 5;
    int inc = v;
#pragma unroll
    for (int off = 1; off < 32; off <<= 1) {
        int u = __shfl_up_sync(0xffffffffu, inc, off);
        if (lane >= off) inc += u;
    }
    __shared__ int w0tot;
    if (wid == 0 && lane == 31) w0tot = inc;
    __syncthreads();
    if (wid == 1) inc += w0tot;
    if (t < SCAN_B) g_boff[t] = inc - v;  // exclusive
    if (t == 0) g_rowptr[NN] = EE;
}

// phase 3: per-block exclusive scan + apply spine offset -> rowptr, woff
__global__ __launch_bounds__(1024) void scan_apply_kernel() {
    int i = blockIdx.x * 1024 + threadIdx.x;
    int v = (i < NN) ? g_cnt[i] : 0;
    int lane = threadIdx.x & 31, wid = threadIdx.x >> 5;
    int inc = v;
#pragma unroll
    for (int off = 1; off < 32; off <<= 1) {
        int u = __shfl_up_sync(0xffffffffu, inc, off);
        if (lane >= off) inc += u;
    }
    __shared__ int ws[32];
    if (lane == 31) ws[wid] = inc;
    __syncthreads();
    if (wid == 0) {
        int u = ws[lane];
#pragma unroll
        for (int off = 1; off < 32; off <<= 1) {
            int z = __shfl_up_sync(0xffffffffu, u, off);
            if (lane >= off) u += z;
        }
        ws[lane] = u;
    }
    __syncthreads();
    int excl = (wid > 0 ? ws[wid - 1] : 0) + inc - v + g_boff[blockIdx.x];
    if (i < NN) {
        g_rowptr[i] = excl;
        g_woff[i] = excl;
    }
}

// compute norm + place into CSR buckets
__global__ __launch_bounds__(256) void place_kernel(const float* __restrict__ ea) {
    int e = blockIdx.x * blockDim.x + threadIdx.x;
    if (e >= EE) return;
    int s = g_src[e];
    int d = g_dst[e];
    float ds = g_deg[s];
    float dd = g_deg[d];
    float ns = ds > 0.0f ? rsqrtf(ds) : 0.0f;
    float nd = dd > 0.0f ? rsqrtf(dd) : 0.0f;
    int pos = atomicAdd(&g_woff[d], 1);
    g_cs_src[pos] = s;
    g_cs_val[pos] = ns * ea[e] * nd;
}

__global__ __launch_bounds__(256) void concat_kernel(const float* __restrict__ x,
                                                     const float* __restrict__ pos) {
    int n = blockIdx.x * blockDim.x + threadIdx.x;
    if (n < NN) {
        float* o = &g_h0a[n * 8];
#pragma unroll
        for (int i = 0; i < 6; i++) o[i] = x[n * 6 + i];
        o[6] = pos[n * 2 + 0];
        o[7] = pos[n * 2 + 1];
    }
}

// ---------------- CSR gather hops ----------------
// F=64: warp per node, lane owns features {lane, lane+32}; 4-edge unroll for MLP
__global__ __launch_bounds__(256) void gather64_kernel(const float* __restrict__ hin,
                                                       float* __restrict__ hout) {
    int warp = (blockIdx.x * blockDim.x + threadIdx.x) >> 5;
    int lane = threadIdx.x & 31;
    if (warp >= NN) return;
    int beg = g_rowptr[warp];
    int end = g_rowptr[warp + 1];
    float a00 = 0.0f, a01 = 0.0f, a10 = 0.0f, a11 = 0.0f;
    float a20 = 0.0f, a21 = 0.0f, a30 = 0.0f, a31 = 0.0f;
    for (int b = beg; b < end; b += 32) {
        int idx = b + lane;
        int s = (idx < end) ? g_cs_src[idx] : 0;
        float w = (idx < end) ? g_cs_val[idx] : 0.0f;
        int m = min(32, end - b);
        int j = 0;
        for (; j + 4 <= m; j += 4) {
            int s0 = __shfl_sync(0xffffffffu, s, j + 0);
            int s1 = __shfl_sync(0xffffffffu, s, j + 1);
            int s2 = __shfl_sync(0xffffffffu, s, j + 2);
            int s3 = __shfl_sync(0xffffffffu, s, j + 3);
            float w0 = __shfl_sync(0xffffffffu, w, j + 0);
            float w1 = __shfl_sync(0xffffffffu, w, j + 1);
            float w2 = __shfl_sync(0xffffffffu, w, j + 2);
            float w3 = __shfl_sync(0xffffffffu, w, j + 3);
            const float* r0 = hin + s0 * 64;
            const float* r1 = hin + s1 * 64;
            const float* r2 = hin + s2 * 64;
            const float* r3 = hin + s3 * 64;
            float v00 = r0[lane], v01 = r0[lane + 32];
            float v10 = r1[lane], v11 = r1[lane + 32];
            float v20 = r2[lane], v21 = r2[lane + 32];
            float v30 = r3[lane], v31 = r3[lane + 32];
            a00 = fmaf(w0, v00, a00); a01 = fmaf(w0, v01, a01);
            a10 = fmaf(w1, v10, a10); a11 = fmaf(w1, v11, a11);
            a20 = fmaf(w2, v20, a20); a21 = fmaf(w2, v21, a21);
            a30 = fmaf(w3, v30, a30); a31 = fmaf(w3, v31, a31);
        }
        for (; j < m; j++) {
            int sj = __shfl_sync(0xffffffffu, s, j);
            float wj = __shfl_sync(0xffffffffu, w, j);
            const float* row = hin + sj * 64;
            a00 = fmaf(wj, row[lane], a00);
            a01 = fmaf(wj, row[lane + 32], a01);
        }
    }
    float f0 = (a00 + a10) + (a20 + a30);
    float f1 = (a01 + a11) + (a21 + a31);
    hout[warp * 64 + lane] = f0;
    hout[warp * 64 + lane + 32] = f1;
}

// small-F gathers: thread per (node, feature), 2-edge unroll
template <int F>
__global__ __launch_bounds__(256) void gatherF_kernel(const float* __restrict__ hin,
                                                      float* __restrict__ hout) {
    int tid = blockIdx.x * blockDim.x + threadIdx.x;
    if (tid >= NN * F) return;
    int n = tid / F;
    int f = tid - n * F;
    int beg = g_rowptr[n];
    int end = g_rowptr[n + 1];
    float a0 = 0.0f, a1 = 0.0f;
    int e = beg;
    for (; e + 2 <= end; e += 2) {
        a0 = fmaf(g_cs_val[e], hin[g_cs_src[e] * F + f], a0);
        a1 = fmaf(g_cs_val[e + 1], hin[g_cs_src[e + 1] * F + f], a1);
    }
    if (e < end) a0 = fmaf(g_cs_val[e], hin[g_cs_src[e] * F + f], a0);
    hout[tid] = a0 + a1;
}

// ---------------- dense GEMMs ----------------
template <int FIN, int FOUT, bool RELU>
__global__ __launch_bounds__(256) void gemm4v_kernel(const float* __restrict__ h0,
                                                     const float* __restrict__ h1,
                                                     const float* __restrict__ h2,
                                                     const float* __restrict__ h3,
                                                     const float* __restrict__ W,
                                                     const float* __restrict__ b,
                                                     float* __restrict__ out) {
    constexpr int J4 = FOUT / 4;
    int tid = blockIdx.x * blockDim.x + threadIdx.x;
    if (tid >= NN * J4) return;
    int n = tid / J4;
    int j = (tid - n * J4) * 4;
    float4 acc = *(const float4*)&b[j];
    const float* hs[4] = {h0 + n * FIN, h1 + n * FIN, h2 + n * FIN, h3 + n * FIN};
#pragma unroll
    for (int k = 0; k < 4; k++) {
        const float* h = hs[k];
        const float* w = W + k * FIN * FOUT + j;
#pragma unroll
        for (int f = 0; f < FIN; f++) {
            float hf = h[f];
            float4 wv = *(const float4*)&w[f * FOUT];
            acc.x = fmaf(hf, wv.x, acc.x);
            acc.y = fmaf(hf, wv.y, acc.y);
            acc.z = fmaf(hf, wv.z, acc.z);
            acc.w = fmaf(hf, wv.w, acc.w);
        }
    }
    if (RELU) {
        acc.x = fmaxf(acc.x, 0.0f); acc.y = fmaxf(acc.y, 0.0f);
        acc.z = fmaxf(acc.z, 0.0f); acc.w = fmaxf(acc.w, 0.0f);
    }
    *(float4*)&out[n * FOUT + j] = acc;
}

// plain gemm slice: out = h @ W  (FIN=64, FOUT=10)
__global__ __launch_bounds__(256) void gemm10_kernel(const float* __restrict__ h,
                                                     const float* __restrict__ W,
                                                     float* __restrict__ out) {
    int tid = blockIdx.x * blockDim.x + threadIdx.x;
    if (tid >= NN * 10) return;
    int n = tid / 10;
    int j = tid - n * 10;
    float acc = 0.0f;
    const float* hr = h + n * 64;
#pragma unroll
    for (int f = 0; f < 64; f++) acc = fmaf(hr[f], W[f * 10 + j], acc);
    out[tid] = acc;
}

// fused Horner step: out[n][j] = gatherA(p)[n][j] + h[n]·W[:,j] (+bias)
template <bool BIAS>
__global__ __launch_bounds__(256) void gather_gemm10_kernel(const float* __restrict__ p,
                                                            const float* __restrict__ h,
                                                            const float* __restrict__ W,
                                                            const float* __restrict__ b,
                                                            float* __restrict__ out) {
    int tid = blockIdx.x * blockDim.x + threadIdx.x;
    if (tid >= NN * 10) return;
    int n = tid / 10;
    int j = tid - n * 10;
    int beg = g_rowptr[n];
    int end = g_rowptr[n + 1];
    float a0 = 0.0f, a1 = 0.0f;
    int e = beg;
    for (; e + 2 <= end; e += 2) {
        a0 = fmaf(g_cs_val[e], p[g_cs_src[e] * 10 + j], a0);
        a1 = fmaf(g_cs_val[e + 1], p[g_cs_src[e + 1] * 10 + j], a1);
    }
    if (e < end) a0 = fmaf(g_cs_val[e], p[g_cs_src[e] * 10 + j], a0);
    float acc = a0 + a1;
    if (BIAS) acc += b[j];
    const float* hr = h + n * 64;
#pragma unroll
    for (int f = 0; f < 64; f++) acc = fmaf(hr[f], W[f * 10 + j], acc);
    out[tid] = acc;
}

__global__ __launch_bounds__(256) void logsoftmax_kernel(float* __restrict__ out) {
    int n = blockIdx.x * blockDim.x + threadIdx.x;
    if (n >= NN) return;
    float v[10];
    float m = -1e30f;
#pragma unroll
    for (int i = 0; i < 10; i++) {
        v[i] = out[n * 10 + i];
        m = fmaxf(m, v[i]);
    }
    float s = 0.0f;
#pragma unroll
    for (int i = 0; i < 10; i++) s += expf(v[i] - m);
    float l = logf(s) + m;
#pragma unroll
    for (int i = 0; i < 10; i++) out[n * 10 + i] = v[i] - l;
}

// ---------------- host ----------------
static inline int cdiv(int a, int b) { return (a + b - 1) / b; }

extern "C" void kernel_launch(void* const* d_in, const int* in_sizes, int n_in,
                              void* d_out, int out_size) {
    const float* x   = (const float*)d_in[0];
    const float* pos = (const float*)d_in[1];
    const float* ea  = (const float*)d_in[2];
    const float* W1  = (const float*)d_in[3];
    const float* b1  = (const float*)d_in[4];
    const float* W2  = (const float*)d_in[5];
    const float* b2  = (const float*)d_in[6];
    const float* W3  = (const float*)d_in[7];
    const float* b3  = (const float*)d_in[8];
    const int* ei    = (const int*)d_in[9];
    float* out = (float*)d_out;

    float *h0a, *h0b, *h1, *h2, *h3;
    cudaGetSymbolAddress((void**)&h0a, g_h0a);
    cudaGetSymbolAddress((void**)&h0b, g_h0b);
    cudaGetSymbolAddress((void**)&h1, g_h1);
    cudaGetSymbolAddress((void**)&h2, g_h2);
    cudaGetSymbolAddress((void**)&h3, g_h3);

    const int B = 256;

    // preprocessing: indices -> deg/cnt -> scan -> CSR place
    detect_kernel<<<1, 1>>>(ei);
    build_zero_kernel<<<cdiv(EE, B), B>>>(ei);
    degcnt_kernel<<<cdiv(EE, B), B>>>(ea);
    scan_reduce_kernel<<<SCAN_B, 1024>>>();
    scan_spine_kernel<<<1, 64>>>();
    scan_apply_kernel<<<SCAN_B, 1024>>>();
    place_kernel<<<cdiv(EE, B), B>>>(ea);
    concat_kernel<<<cdiv(NN, B), B>>>(x, pos);

    // ---------------- layer 1: 8 -> 64, ReLU (hops at F=8) ----------------
    gatherF_kernel<8><<<cdiv(NN * 8, B), B>>>(h0a, h1);
    gatherF_kernel<8><<<cdiv(NN * 8, B), B>>>(h1, h2);
    gatherF_kernel<8><<<cdiv(NN * 8, B), B>>>(h2, h3);
    gemm4v_kernel<8, 64, true><<<cdiv(NN * 16, B), B>>>(h0a, h1, h2, h3, W1, b1, h0b);

    // ---------------- layer 2: 64 -> 64, ReLU (hops at F=64) ----------------
    gather64_kernel<<<cdiv(NN * 32, B), B>>>(h0b, h1);
    gather64_kernel<<<cdiv(NN * 32, B), B>>>(h1, h2);
    gather64_kernel<<<cdiv(NN * 32, B), B>>>(h2, h3);
    gemm4v_kernel<64, 64, true><<<cdiv(NN * 16, B), B>>>(h0b, h1, h2, h3, W2, b2, h0a);

    // ---------------- layer 3 (Horner, fused): hops at F=10 ----------------
    // t = hW3; t = hW2 + At; t = hW1 + At; out = hW0 + b + At; logsoftmax
    float* p = h1;
    float* q = h2;
    gemm10_kernel<<<cdiv(NN * 10, B), B>>>(h0a, W3 + 3 * 640, p);
    gather_gemm10_kernel<false><<<cdiv(NN * 10, B), B>>>(p, h0a, W3 + 2 * 640, nullptr, q);
    gather_gemm10_kernel<false><<<cdiv(NN * 10, B), B>>>(q, h0a, W3 + 1 * 640, nullptr, p);
    gather_gemm10_kernel<true><<<cdiv(NN * 10, B), B>>>(p, h0a, W3, b3, out);

    logsoftmax_kernel<<<cdiv(NN, B), B>>>(out);
}

// round 11
// speedup vs baseline: 2.9548x; 1.0810x over previous
#include <cuda_runtime.h>
#include <math.h>

#define NN 50000
#define EE 800000
#define SCAN_B 49  // ceil(NN/1024)

// ---------------- scratch (device globals; no allocation) ----------------
__device__ int   g_is64;
__device__ float g_deg[NN];
__device__ int   g_src[EE];
__device__ int   g_dst[EE];
__device__ int   g_cnt[NN];
__device__ int   g_bsum[SCAN_B];
__device__ int   g_rowptr[NN + 1];
__device__ int   g_woff[NN];
__device__ int   g_cs_src[EE];
__device__ float g_cs_val[EE];
__device__ float g_h0a[NN * 64];
__device__ float g_h0b[NN * 64];
__device__ float g_h1[NN * 64];
__device__ float g_h2[NN * 64];
__device__ float g_h3[NN * 64];

// packed f32x2 helpers
#define FMA_F32X2(d, a, b, c) \
    asm("fma.rn.f32x2 %0, %1, %2, %3;" : "=l"(d) : "l"(a), "l"(b), "l"(c))
#define PACK2_SPLAT(d, r) \
    asm("mov.b64 %0, {%1, %1};" : "=l"(d) : "r"(r))
#define PACK2(d, lo, hi) \
    asm("mov.b64 %0, {%1, %2};" : "=l"(d) : "r"(lo), "r"(hi))

// ---------------- preprocessing ----------------
__global__ void detect_kernel(const int* __restrict__ w) {
    int allzero = 1;
    for (int i = 1; i < 1024; i += 2)
        if (w[i] != 0) { allzero = 0; break; }
    g_is64 = allzero;
}

__global__ __launch_bounds__(256) void build_zero_kernel(const int* __restrict__ w) {
    int e = blockIdx.x * blockDim.x + threadIdx.x;
    if (e < EE) {
        int s, d;
        if (g_is64) { s = w[2 * e]; d = w[2 * (EE + e)]; }
        else        { s = w[e];     d = w[EE + e]; }
        g_src[e] = s;
        g_dst[e] = d;
    }
    if (e < NN) { g_deg[e] = 0.0f; g_cnt[e] = 0; }
}

__global__ __launch_bounds__(256) void degcnt_kernel(const float* __restrict__ ea) {
    int e = blockIdx.x * blockDim.x + threadIdx.x;
    if (e < EE) {
        int d = g_dst[e];
        atomicAdd(&g_deg[d], ea[e]);
        atomicAdd(&g_cnt[d], 1);
    }
}

// scan phase 1: per-block reduce of 1024 cnt values
__global__ __launch_bounds__(1024) void scan_reduce_kernel() {
    int i = blockIdx.x * 1024 + threadIdx.x;
    int v = (i < NN) ? g_cnt[i] : 0;
    int lane = threadIdx.x & 31, wid = threadIdx.x >> 5;
#pragma unroll
    for (int off = 16; off > 0; off >>= 1) v += __shfl_down_sync(0xffffffffu, v, off);
    __shared__ int ws[32];
    if (lane == 0) ws[wid] = v;
    __syncthreads();
    if (wid == 0) {
        int u = ws[lane];
#pragma unroll
        for (int off = 16; off > 0; off >>= 1) u += __shfl_down_sync(0xffffffffu, u, off);
        if (lane == 0) g_bsum[blockIdx.x] = u;
    }
}

// scan phase 2 (spine fused): per-block scan + apply spine offset -> rowptr, woff
__global__ __launch_bounds__(1024) void scan_apply_kernel() {
    __shared__ int boff_s;
    int lane = threadIdx.x & 31, wid = threadIdx.x >> 5;
    // warp 0 computes sum of g_bsum[0..bid-1]
    if (wid == 0) {
        int bid = blockIdx.x;
        int v = 0;
        if (lane < bid) v += g_bsum[lane];
        if (lane + 32 < bid) v += g_bsum[lane + 32];
#pragma unroll
        for (int off = 16; off > 0; off >>= 1) v += __shfl_down_sync(0xffffffffu, v, off);
        if (lane == 0) boff_s = v;
    }
    int i = blockIdx.x * 1024 + threadIdx.x;
    int v = (i < NN) ? g_cnt[i] : 0;
    int inc = v;
#pragma unroll
    for (int off = 1; off < 32; off <<= 1) {
        int u = __shfl_up_sync(0xffffffffu, inc, off);
        if (lane >= off) inc += u;
    }
    __shared__ int ws[32];
    if (lane == 31) ws[wid] = inc;
    __syncthreads();
    if (wid == 0) {
        int u = ws[lane];
#pragma unroll
        for (int off = 1; off < 32; off <<= 1) {
            int z = __shfl_up_sync(0xffffffffu, u, off);
            if (lane >= off) u += z;
        }
        ws[lane] = u;
    }
    __syncthreads();
    int excl = (wid > 0 ? ws[wid - 1] : 0) + inc - v + boff_s;
    if (i < NN) {
        g_rowptr[i] = excl;
        g_woff[i] = excl;
    }
    if (i == 0) g_rowptr[NN] = EE;
}

// compute norm + place into CSR buckets
__global__ __launch_bounds__(256) void place_kernel(const float* __restrict__ ea) {
    int e = blockIdx.x * blockDim.x + threadIdx.x;
    if (e >= EE) return;
    int s = g_src[e];
    int d = g_dst[e];
    float ds = g_deg[s];
    float dd = g_deg[d];
    float ns = ds > 0.0f ? rsqrtf(ds) : 0.0f;
    float nd = dd > 0.0f ? rsqrtf(dd) : 0.0f;
    int pos = atomicAdd(&g_woff[d], 1);
    g_cs_src[pos] = s;
    g_cs_val[pos] = ns * ea[e] * nd;
}

__global__ __launch_bounds__(256) void concat_kernel(const float* __restrict__ x,
                                                     const float* __restrict__ pos) {
    int n = blockIdx.x * blockDim.x + threadIdx.x;
    if (n < NN) {
        float* o = &g_h0a[n * 8];
#pragma unroll
        for (int i = 0; i < 6; i++) o[i] = x[n * 6 + i];
        o[6] = pos[n * 2 + 0];
        o[7] = pos[n * 2 + 1];
    }
}

// ---------------- CSR gather hops ----------------
__global__ __launch_bounds__(256) void gather64_kernel(const float* __restrict__ hin,
                                                       float* __restrict__ hout) {
    int warp = (blockIdx.x * blockDim.x + threadIdx.x) >> 5;
    int lane = threadIdx.x & 31;
    if (warp >= NN) return;
    int beg = g_rowptr[warp];
    int end = g_rowptr[warp + 1];
    float a00 = 0.0f, a01 = 0.0f, a10 = 0.0f, a11 = 0.0f;
    float a20 = 0.0f, a21 = 0.0f, a30 = 0.0f, a31 = 0.0f;
    for (int b = beg; b < end; b += 32) {
        int idx = b + lane;
        int s = (idx < end) ? g_cs_src[idx] : 0;
        float w = (idx < end) ? g_cs_val[idx] : 0.0f;
        int m = min(32, end - b);
        int j = 0;
        for (; j + 4 <= m; j += 4) {
            int s0 = __shfl_sync(0xffffffffu, s, j + 0);
            int s1 = __shfl_sync(0xffffffffu, s, j + 1);
            int s2 = __shfl_sync(0xffffffffu, s, j + 2);
            int s3 = __shfl_sync(0xffffffffu, s, j + 3);
            float w0 = __shfl_sync(0xffffffffu, w, j + 0);
            float w1 = __shfl_sync(0xffffffffu, w, j + 1);
            float w2 = __shfl_sync(0xffffffffu, w, j + 2);
            float w3 = __shfl_sync(0xffffffffu, w, j + 3);
            const float* r0 = hin + s0 * 64;
            const float* r1 = hin + s1 * 64;
            const float* r2 = hin + s2 * 64;
            const float* r3 = hin + s3 * 64;
            float v00 = r0[lane], v01 = r0[lane + 32];
            float v10 = r1[lane], v11 = r1[lane + 32];
            float v20 = r2[lane], v21 = r2[lane + 32];
            float v30 = r3[lane], v31 = r3[lane + 32];
            a00 = fmaf(w0, v00, a00); a01 = fmaf(w0, v01, a01);
            a10 = fmaf(w1, v10, a10); a11 = fmaf(w1, v11, a11);
            a20 = fmaf(w2, v20, a20); a21 = fmaf(w2, v21, a21);
            a30 = fmaf(w3, v30, a30); a31 = fmaf(w3, v31, a31);
        }
        for (; j < m; j++) {
            int sj = __shfl_sync(0xffffffffu, s, j);
            float wj = __shfl_sync(0xffffffffu, w, j);
            const float* row = hin + sj * 64;
            a00 = fmaf(wj, row[lane], a00);
            a01 = fmaf(wj, row[lane + 32], a01);
        }
    }
    float f0 = (a00 + a10) + (a20 + a30);
    float f1 = (a01 + a11) + (a21 + a31);
    hout[warp * 64 + lane] = f0;
    hout[warp * 64 + lane + 32] = f1;
}

template <int F>
__global__ __launch_bounds__(256) void gatherF_kernel(const float* __restrict__ hin,
                                                      float* __restrict__ hout) {
    int tid = blockIdx.x * blockDim.x + threadIdx.x;
    if (tid >= NN * F) return;
    int n = tid / F;
    int f = tid - n * F;
    int beg = g_rowptr[n];
    int end = g_rowptr[n + 1];
    float a0 = 0.0f, a1 = 0.0f;
    int e = beg;
    for (; e + 2 <= end; e += 2) {
        a0 = fmaf(g_cs_val[e], hin[g_cs_src[e] * F + f], a0);
        a1 = fmaf(g_cs_val[e + 1], hin[g_cs_src[e + 1] * F + f], a1);
    }
    if (e < end) a0 = fmaf(g_cs_val[e], hin[g_cs_src[e] * F + f], a0);
    hout[tid] = a0 + a1;
}

// ---------------- layer-1 GEMM (8 -> 64) ----------------
template <int FIN, int FOUT, bool RELU>
__global__ __launch_bounds__(256) void gemm4v_kernel(const float* __restrict__ h0,
                                                     const float* __restrict__ h1,
                                                     const float* __restrict__ h2,
                                                     const float* __restrict__ h3,
                                                     const float* __restrict__ W,
                                                     const float* __restrict__ b,
                                                     float* __restrict__ out) {
    constexpr int J4 = FOUT / 4;
    int tid = blockIdx.x * blockDim.x + threadIdx.x;
    if (tid >= NN * J4) return;
    int n = tid / J4;
    int j = (tid - n * J4) * 4;
    float4 acc = *(const float4*)&b[j];
    const float* hs[4] = {h0 + n * FIN, h1 + n * FIN, h2 + n * FIN, h3 + n * FIN};
#pragma unroll
    for (int k = 0; k < 4; k++) {
        const float* h = hs[k];
        const float* w = W + k * FIN * FOUT + j;
#pragma unroll
        for (int f = 0; f < FIN; f++) {
            float hf = h[f];
            float4 wv = *(const float4*)&w[f * FOUT];
            acc.x = fmaf(hf, wv.x, acc.x);
            acc.y = fmaf(hf, wv.y, acc.y);
            acc.z = fmaf(hf, wv.z, acc.z);
            acc.w = fmaf(hf, wv.w, acc.w);
        }
    }
    if (RELU) {
        acc.x = fmaxf(acc.x, 0.0f); acc.y = fmaxf(acc.y, 0.0f);
        acc.z = fmaxf(acc.z, 0.0f); acc.w = fmaxf(acc.w, 0.0f);
    }
    *(float4*)&out[n * FOUT + j] = acc;
}

// ---------------- layer-2 GEMM (64 -> 64) with packed f32x2 FMA ----------------
// block = 128 threads -> tile 128 nodes x 64 cols.
// thread: colgroup c = t&3 (cols c*16..c*16+15), nodegroup g = t>>2 (nodes g*4..g*4+3)
__global__ __launch_bounds__(128) void gemm64_ffma2_kernel(const float* __restrict__ h0,
                                                           const float* __restrict__ h1,
                                                           const float* __restrict__ h2,
                                                           const float* __restrict__ h3,
                                                           const float* __restrict__ W,
                                                           const float* __restrict__ b,
                                                           float* __restrict__ out) {
    __shared__ float wsm[64 * 64];       // 16 KB (one k-slice)
    __shared__ float hsm[128 * 65];      // 33.3 KB (padded rows: conflict-free splats)
    int t = threadIdx.x;
    int c = t & 3;
    int g = t >> 2;
    int n0 = blockIdx.x * 128;
    int c16 = c * 16;
    int g4 = g * 4;

    unsigned long long acc[4][8];
    // init with bias pairs
#pragma unroll
    for (int u = 0; u < 8; u++) {
        unsigned int blo = __float_as_uint(b[c16 + 2 * u]);
        unsigned int bhi = __float_as_uint(b[c16 + 2 * u + 1]);
        unsigned long long bp;
        PACK2(bp, blo, bhi);
#pragma unroll
        for (int ni = 0; ni < 4; ni++) acc[ni][u] = bp;
    }

    const float* hks[4] = {h0, h1, h2, h3};
#pragma unroll 1
    for (int k = 0; k < 4; k++) {
        __syncthreads();
        const float* hk = hks[k];
        // stage h tile (coalesced) and W slice
        for (int idx = t; idx < 128 * 64; idx += 128) {
            int i = idx >> 6, f = idx & 63;
            int n = n0 + i;
            hsm[i * 65 + f] = (n < NN) ? hk[n * 64 + f] : 0.0f;
        }
        for (int idx = t; idx < 64 * 64; idx += 128) wsm[idx] = W[k * 4096 + idx];
        __syncthreads();

#pragma unroll 4
        for (int f = 0; f < 64; f++) {
            unsigned long long hv[4];
#pragma unroll
            for (int ni = 0; ni < 4; ni++) {
                unsigned int hb = __float_as_uint(hsm[(g4 + ni) * 65 + f]);
                PACK2_SPLAT(hv[ni], hb);
            }
            const float* wr = &wsm[f * 64 + c16];
            ulonglong2 wa = *(const ulonglong2*)(wr + 0);
            ulonglong2 wb = *(const ulonglong2*)(wr + 4);
            ulonglong2 wc = *(const ulonglong2*)(wr + 8);
            ulonglong2 wd = *(const ulonglong2*)(wr + 12);
            unsigned long long wp[8] = {wa.x, wa.y, wb.x, wb.y, wc.x, wc.y, wd.x, wd.y};
#pragma unroll
            for (int ni = 0; ni < 4; ni++) {
#pragma unroll
                for (int u = 0; u < 8; u++) {
                    FMA_F32X2(acc[ni][u], hv[ni], wp[u], acc[ni][u]);
                }
            }
        }
    }

    // epilogue: relu + store
#pragma unroll
    for (int ni = 0; ni < 4; ni++) {
        int n = n0 + g4 + ni;
        if (n >= NN) continue;
        float* o = out + n * 64 + c16;
#pragma unroll
        for (int v = 0; v < 4; v++) {
            unsigned long long p0 = acc[ni][2 * v];
            unsigned long long p1 = acc[ni][2 * v + 1];
            float4 r;
            r.x = fmaxf(__uint_as_float((unsigned)(p0 & 0xffffffffull)), 0.0f);
            r.y = fmaxf(__uint_as_float((unsigned)(p0 >> 32)), 0.0f);
            r.z = fmaxf(__uint_as_float((unsigned)(p1 & 0xffffffffull)), 0.0f);
            r.w = fmaxf(__uint_as_float((unsigned)(p1 >> 32)), 0.0f);
            *(float4*)(o + 4 * v) = r;
        }
    }
}

// ---------------- layer-3 Horner pieces ----------------
__global__ __launch_bounds__(256) void gemm10_kernel(const float* __restrict__ h,
                                                     const float* __restrict__ W,
                                                     float* __restrict__ out) {
    int tid = blockIdx.x * blockDim.x + threadIdx.x;
    if (tid >= NN * 10) return;
    int n = tid / 10;
    int j = tid - n * 10;
    float acc = 0.0f;
    const float* hr = h + n * 64;
#pragma unroll
    for (int f = 0; f < 64; f++) acc = fmaf(hr[f], W[f * 10 + j], acc);
    out[tid] = acc;
}

__global__ __launch_bounds__(256) void gather_gemm10_kernel(const float* __restrict__ p,
                                                            const float* __restrict__ h,
                                                            const float* __restrict__ W,
                                                            float* __restrict__ out) {
    int tid = blockIdx.x * blockDim.x + threadIdx.x;
    if (tid >= NN * 10) return;
    int n = tid / 10;
    int j = tid - n * 10;
    int beg = g_rowptr[n];
    int end = g_rowptr[n + 1];
    float a0 = 0.0f, a1 = 0.0f;
    int e = beg;
    for (; e + 2 <= end; e += 2) {
        a0 = fmaf(g_cs_val[e], p[g_cs_src[e] * 10 + j], a0);
        a1 = fmaf(g_cs_val[e + 1], p[g_cs_src[e + 1] * 10 + j], a1);
    }
    if (e < end) a0 = fmaf(g_cs_val[e], p[g_cs_src[e] * 10 + j], a0);
    float acc = a0 + a1;
    const float* hr = h + n * 64;
#pragma unroll
    for (int f = 0; f < 64; f++) acc = fmaf(hr[f], W[f * 10 + j], acc);
    out[tid] = acc;
}

// final step fused with bias + log_softmax: thread per node
__global__ __launch_bounds__(256) void gg10_lsm_kernel(const float* __restrict__ p,
                                                       const float* __restrict__ h,
                                                       const float* __restrict__ W,
                                                       const float* __restrict__ b,
                                                       float* __restrict__ out) {
    int n = blockIdx.x * blockDim.x + threadIdx.x;
    if (n >= NN) return;
    float acc[10];
#pragma unroll
    for (int j = 0; j < 10; j++) acc[j] = b[j];
    // dense part: h[n] @ W0
    const float4* hr = (const float4*)(h + n * 64);
#pragma unroll
    for (int q = 0; q < 16; q++) {
        float4 hv = hr[q];
        const float* w0 = W + (4 * q) * 10;
#pragma unroll
        for (int j = 0; j < 10; j++) {
            acc[j] = fmaf(hv.x, w0[j], acc[j]);
            acc[j] = fmaf(hv.y, w0[10 + j], acc[j]);
            acc[j] = fmaf(hv.z, w0[20 + j], acc[j]);
            acc[j] = fmaf(hv.w, w0[30 + j], acc[j]);
        }
    }
    // gather part
    int beg = g_rowptr[n];
    int end = g_rowptr[n + 1];
    for (int e = beg; e < end; e++) {
        float w = g_cs_val[e];
        const float2* pr = (const float2*)(p + g_cs_src[e] * 10);
#pragma unroll
        for (int q = 0; q < 5; q++) {
            float2 pv = pr[q];
            acc[2 * q] = fmaf(w, pv.x, acc[2 * q]);
            acc[2 * q + 1] = fmaf(w, pv.y, acc[2 * q + 1]);
        }
    }
    // log_softmax
    float m = -1e30f;
#pragma unroll
    for (int j = 0; j < 10; j++) m = fmaxf(m, acc[j]);
    float s = 0.0f;
#pragma unroll
    for (int j = 0; j < 10; j++) s += expf(acc[j] - m);
    float l = logf(s) + m;
    float2* o = (float2*)(out + n * 10);
#pragma unroll
    for (int q = 0; q < 5; q++) {
        float2 r;
        r.x = acc[2 * q] - l;
        r.y = acc[2 * q + 1] - l;
        o[q] = r;
    }
}

// ---------------- host ----------------
static inline int cdiv(int a, int b) { return (a + b - 1) / b; }

extern "C" void kernel_launch(void* const* d_in, const int* in_sizes, int n_in,
                              void* d_out, int out_size) {
    const float* x   = (const float*)d_in[0];
    const float* pos = (const float*)d_in[1];
    const float* ea  = (const float*)d_in[2];
    const float* W1  = (const float*)d_in[3];
    const float* b1  = (const float*)d_in[4];
    const float* W2  = (const float*)d_in[5];
    const float* b2  = (const float*)d_in[6];
    const float* W3  = (const float*)d_in[7];
    const float* b3  = (const float*)d_in[8];
    const int* ei    = (const int*)d_in[9];
    float* out = (float*)d_out;

    float *h0a, *h0b, *h1, *h2, *h3;
    cudaGetSymbolAddress((void**)&h0a, g_h0a);
    cudaGetSymbolAddress((void**)&h0b, g_h0b);
    cudaGetSymbolAddress((void**)&h1, g_h1);
    cudaGetSymbolAddress((void**)&h2, g_h2);
    cudaGetSymbolAddress((void**)&h3, g_h3);

    const int B = 256;

    // preprocessing: indices -> deg/cnt -> scan -> CSR place
    detect_kernel<<<1, 1>>>(ei);
    build_zero_kernel<<<cdiv(EE, B), B>>>(ei);
    degcnt_kernel<<<cdiv(EE, B), B>>>(ea);
    scan_reduce_kernel<<<SCAN_B, 1024>>>();
    scan_apply_kernel<<<SCAN_B, 1024>>>();
    place_kernel<<<cdiv(EE, B), B>>>(ea);
    concat_kernel<<<cdiv(NN, B), B>>>(x, pos);

    // ---------------- layer 1: 8 -> 64, ReLU (hops at F=8) ----------------
    gatherF_kernel<8><<<cdiv(NN * 8, B), B>>>(h0a, h1);
    gatherF_kernel<8><<<cdiv(NN * 8, B), B>>>(h1, h2);
    gatherF_kernel<8><<<cdiv(NN * 8, B), B>>>(h2, h3);
    gemm4v_kernel<8, 64, true><<<cdiv(NN * 16, B), B>>>(h0a, h1, h2, h3, W1, b1, h0b);

    // ---------------- layer 2: 64 -> 64, ReLU (hops at F=64) ----------------
    gather64_kernel<<<cdiv(NN * 32, B), B>>>(h0b, h1);
    gather64_kernel<<<cdiv(NN * 32, B), B>>>(h1, h2);
    gather64_kernel<<<cdiv(NN * 32, B), B>>>(h2, h3);
    gemm64_ffma2_kernel<<<cdiv(NN, 128), 128>>>(h0b, h1, h2, h3, W2, b2, h0a);

    // ---------------- layer 3 (Horner, fused): hops at F=10 ----------------
    float* p = h1;
    float* q = h2;
    gemm10_kernel<<<cdiv(NN * 10, B), B>>>(h0a, W3 + 3 * 640, p);
    gather_gemm10_kernel<<<cdiv(NN * 10, B), B>>>(p, h0a, W3 + 2 * 640, q);
    gather_gemm10_kernel<<<cdiv(NN * 10, B), B>>>(q, h0a, W3 + 1 * 640, p);
    gg10_lsm_kernel<<<cdiv(NN, B), B>>>(p, h0a, W3, b3, out);
}